// round 1
// baseline (speedup 1.0000x reference)
#include <cuda_runtime.h>
#include <cstdint>

// Problem: y2[a,d,z] = sum_c ( sum_b x1[a,b,z]*x0[b,c,z] ) * x2[c,d,z]
// Shapes: all (32,32,32768) fp32, row-major, z contiguous.
// Strategy: fused two-pass per block; y1 kept in 128KB shared memory.
// Each lane handles a packed pair of z values (f32x2), each warp handles 2 'a' rows.
// Block covers 64 z and 16 a-rows; grid (2 a-halves, 512 z-tiles).

#define ZDIM 32768
#define ZH   (ZDIM / 2)          // 16384 f32x2 pairs
#define SDIM 32

using u64 = unsigned long long;

__device__ __forceinline__ u64 ffma2(u64 a, u64 b, u64 c) {
    u64 d;
    asm("fma.rn.f32x2 %0, %1, %2, %3;" : "=l"(d) : "l"(a), "l"(b), "l"(c));
    return d;
}

__global__ void __launch_bounds__(256, 1)
einnet_fused_kernel(const u64* __restrict__ x0,
                    const u64* __restrict__ x1,
                    const u64* __restrict__ x2,
                    u64* __restrict__ out)
{
    // dynamic smem: y1 tile [16 a][32 c][32 z-pairs] of f32x2 = 131072 bytes
    extern __shared__ u64 y1s[];

    const int lane = threadIdx.x & 31;
    const int w    = threadIdx.x >> 5;        // warp id 0..7
    const int half = blockIdx.x;              // a-half: 0 or 1
    const int zt   = blockIdx.y;              // z-tile 0..511

    const int p   = zt * 32 + lane;           // global z-pair index
    const int aL0 = w * 2;                    // local a rows 0..15
    const int aL1 = aL0 + 1;
    const int a0  = half * 16 + aL0;          // global a rows
    const int a1  = a0 + 1;

    u64 acc0[SDIM], acc1[SDIM];
    #pragma unroll
    for (int c = 0; c < SDIM; c++) { acc0[c] = 0ull; acc1[c] = 0ull; }

    // ---------------- Pass 1: y1[a,c] = sum_b x1[a,b] * x0[b,c] ----------------
    const u64* __restrict__ x1p0 = x1 + (size_t)(a0 * SDIM) * ZH + p;
    const u64* __restrict__ x1p1 = x1 + (size_t)(a1 * SDIM) * ZH + p;
    const u64* __restrict__ x0p  = x0 + p;

    for (int b = 0; b < SDIM; b++) {
        const u64 av0 = x1p0[(size_t)b * ZH];
        const u64 av1 = x1p1[(size_t)b * ZH];
        const u64* __restrict__ bp = x0p + (size_t)(b * SDIM) * ZH;
        #pragma unroll
        for (int c = 0; c < SDIM; c++) {
            const u64 bv = bp[(size_t)c * ZH];   // immediate-offset LDG.64
            acc0[c] = ffma2(av0, bv, acc0[c]);
            acc1[c] = ffma2(av1, bv, acc1[c]);
        }
    }

    // stash y1 rows in shared memory (conflict-free: lane-consecutive 8B)
    #pragma unroll
    for (int c = 0; c < SDIM; c++) {
        y1s[(aL0 * SDIM + c) * 32 + lane] = acc0[c];
        y1s[(aL1 * SDIM + c) * 32 + lane] = acc1[c];
    }
    __syncthreads();

    // ---------------- Pass 2: y2[a,d] = sum_c y1[a,c] * x2[c,d] ----------------
    #pragma unroll
    for (int d = 0; d < SDIM; d++) { acc0[d] = 0ull; acc1[d] = 0ull; }

    const u64* __restrict__ x2p = x2 + p;
    for (int c = 0; c < SDIM; c++) {
        const u64 pv0 = y1s[(aL0 * SDIM + c) * 32 + lane];
        const u64 pv1 = y1s[(aL1 * SDIM + c) * 32 + lane];
        const u64* __restrict__ cp = x2p + (size_t)(c * SDIM) * ZH;
        #pragma unroll
        for (int d = 0; d < SDIM; d++) {
            const u64 xv = cp[(size_t)d * ZH];
            acc0[d] = ffma2(pv0, xv, acc0[d]);
            acc1[d] = ffma2(pv1, xv, acc1[d]);
        }
    }

    u64* __restrict__ op0 = out + (size_t)(a0 * SDIM) * ZH + p;
    u64* __restrict__ op1 = out + (size_t)(a1 * SDIM) * ZH + p;
    #pragma unroll
    for (int d = 0; d < SDIM; d++) {
        op0[(size_t)d * ZH] = acc0[d];
        op1[(size_t)d * ZH] = acc1[d];
    }
}

extern "C" void kernel_launch(void* const* d_in, const int* in_sizes, int n_in,
                              void* d_out, int out_size)
{
    (void)in_sizes; (void)n_in; (void)out_size;
    const u64* x0 = (const u64*)d_in[0];   // used as (b, c, Z)
    const u64* x1 = (const u64*)d_in[1];   // used as (a, b, Z)
    const u64* x2 = (const u64*)d_in[2];   // used as (c, d, Z)
    u64* out = (u64*)d_out;

    constexpr int SMEM_BYTES = 16 * 32 * 32 * 8;   // 131072
    // Immediate host-side call; not a stream op, safe under graph capture.
    static bool attr_set = false;
    if (!attr_set) {
        cudaFuncSetAttribute(einnet_fused_kernel,
                             cudaFuncAttributeMaxDynamicSharedMemorySize, SMEM_BYTES);
        attr_set = true;
    }

    dim3 grid(2, ZH / 32);   // (a-half, z-tile) — halves adjacent in linear order
    einnet_fused_kernel<<<grid, 256, SMEM_BYTES>>>(x0, x1, x2, out);
}

// round 3
// speedup vs baseline: 1.3757x; 1.3757x over previous
#include <cuda_runtime.h>
#include <cstdint>

// y2[a,d,z] = sum_c ( sum_b x1[a,b,z]*x0[b,c,z] ) * x2[c,d,z]
// All tensors (32,32,32768) fp32 row-major, z contiguous.
// Fused two-pass, y1 in 64KB smem. Lane = one f32x2 z-pair.
// Warp tile: 4 a-rows x 4 c(or d)-cols -> 16 u64 accumulators (32 regs).
// Block: 256 thr, 8 warps, covers 8 a-rows x 32 z-pairs. 3 blocks/SM.

#define ZH   16384          // z-pairs (f32x2)
#define SDIM 32

using u64 = unsigned long long;

__device__ __forceinline__ u64 ffma2(u64 a, u64 b, u64 c) {
    u64 d;
    asm("fma.rn.f32x2 %0, %1, %2, %3;" : "=l"(d) : "l"(a), "l"(b), "l"(c));
    return d;
}

__global__ void __launch_bounds__(256, 3)
einnet_fused2_kernel(const u64* __restrict__ x0,
                     const u64* __restrict__ x1,
                     const u64* __restrict__ x2,
                     u64* __restrict__ out)
{
    // y1 tile: [aL(8)][c2(16)][zp(32)] of ulonglong2 (c even/odd pair) = 64KB
    extern __shared__ __align__(16) ulonglong2 y1s[];

    const int lane = threadIdx.x & 31;
    const int w    = threadIdx.x >> 5;          // 0..7
    const int abas = blockIdx.x * 8;            // a-group base (0,8,16,24)
    const int p    = blockIdx.y * 32 + lane;    // global z-pair index

    // ---------------- Pass 1: y1[a,c] = sum_b x1[a,b] * x0[b,c] ----------------
    // 16 warp-tiles (2 a-groups x 8 c-groups); warp w does tiles w and w+8.
    #pragma unroll
    for (int t = w; t < 16; t += 8) {
        const int ag = t & 1;
        const int cg = t >> 1;
        const int aL = ag * 4;                  // local a base 0 or 4
        const int c0 = cg * 4;

        u64 acc[4][4];
        #pragma unroll
        for (int i = 0; i < 4; i++)
            #pragma unroll
            for (int j = 0; j < 4; j++) acc[i][j] = 0ull;

        const u64* __restrict__ Ap = x1 + (size_t)(abas + aL) * SDIM * ZH + p;
        const u64* __restrict__ Bp = x0 + (size_t)c0 * ZH + p;

        #pragma unroll 4
        for (int b = 0; b < SDIM; b++) {
            u64 av[4], bv[4];
            #pragma unroll
            for (int i = 0; i < 4; i++) av[i] = Ap[(size_t)(i * SDIM + b) * ZH];
            #pragma unroll
            for (int j = 0; j < 4; j++) bv[j] = Bp[(size_t)(b * SDIM + j) * ZH];
            #pragma unroll
            for (int i = 0; i < 4; i++)
                #pragma unroll
                for (int j = 0; j < 4; j++)
                    acc[i][j] = ffma2(av[i], bv[j], acc[i][j]);
        }

        // store y1 tile: two STS.128 per a-row (c pairs {c0,c0+1},{c0+2,c0+3})
        const int c2 = c0 >> 1;
        #pragma unroll
        for (int i = 0; i < 4; i++) {
            y1s[((aL + i) * 16 + c2)     * 32 + lane] = make_ulonglong2(acc[i][0], acc[i][1]);
            y1s[((aL + i) * 16 + c2 + 1) * 32 + lane] = make_ulonglong2(acc[i][2], acc[i][3]);
        }
    }
    __syncthreads();

    // ---------------- Pass 2: y2[a,d] = sum_c y1[a,c] * x2[c,d] ----------------
    #pragma unroll
    for (int t = w; t < 16; t += 8) {
        const int ag = t & 1;
        const int dg = t >> 1;
        const int aL = ag * 4;
        const int d0 = dg * 4;

        u64 acc[4][4];
        #pragma unroll
        for (int i = 0; i < 4; i++)
            #pragma unroll
            for (int j = 0; j < 4; j++) acc[i][j] = 0ull;

        const u64* __restrict__ Cp = x2 + (size_t)d0 * ZH + p;

        #pragma unroll 2
        for (int c2 = 0; c2 < 16; c2++) {
            ulonglong2 yv[4];
            #pragma unroll
            for (int i = 0; i < 4; i++)
                yv[i] = y1s[((aL + i) * 16 + c2) * 32 + lane];   // LDS.128

            u64 xe[4], xo[4];
            #pragma unroll
            for (int j = 0; j < 4; j++) {
                xe[j] = Cp[(size_t)((2 * c2)     * SDIM + j) * ZH];
                xo[j] = Cp[(size_t)((2 * c2 + 1) * SDIM + j) * ZH];
            }
            #pragma unroll
            for (int i = 0; i < 4; i++)
                #pragma unroll
                for (int j = 0; j < 4; j++) {
                    acc[i][j] = ffma2(yv[i].x, xe[j], acc[i][j]);
                    acc[i][j] = ffma2(yv[i].y, xo[j], acc[i][j]);
                }
        }

        u64* __restrict__ Op = out + (size_t)(abas + aL) * SDIM * ZH + (size_t)d0 * ZH + p;
        #pragma unroll
        for (int i = 0; i < 4; i++)
            #pragma unroll
            for (int j = 0; j < 4; j++)
                Op[(size_t)(i * SDIM + j) * ZH] = acc[i][j];
    }
}

extern "C" void kernel_launch(void* const* d_in, const int* in_sizes, int n_in,
                              void* d_out, int out_size)
{
    (void)in_sizes; (void)n_in; (void)out_size;
    const u64* x0 = (const u64*)d_in[0];   // (b, c, Z)
    const u64* x1 = (const u64*)d_in[1];   // (a, b, Z)
    const u64* x2 = (const u64*)d_in[2];   // (c, d, Z)
    u64* out = (u64*)d_out;

    constexpr int SMEM_BYTES = 8 * 16 * 32 * 16;   // 65536
    // Unconditional: idempotent, not a stream op, capture-safe, no static state.
    cudaFuncSetAttribute(einnet_fused2_kernel,
                         cudaFuncAttributeMaxDynamicSharedMemorySize, SMEM_BYTES);

    // z-tile is the slow grid dimension so the 4 a-group blocks of one z-tile
    // are co-resident and share x0/x2 slices in L1/L2.
    dim3 grid(4, ZH / 32);
    einnet_fused2_kernel<<<grid, 256, SMEM_BYTES>>>(x0, x1, x2, out);
}

// round 4
// speedup vs baseline: 1.9217x; 1.3969x over previous
#include <cuda_runtime.h>
#include <cstdint>

// y2[a,d,z] = sum_c ( sum_b x1[a,b,z]*x0[b,c,z] ) * x2[c,d,z]
// All tensors (32,32,32768) fp32 row-major, z contiguous.
// Fused two-pass, y1 in 64KB smem. Lane = one f32x2 z-pair.
// Warp tile: 8 a-rows x 4 c(or d)-cols -> 32 u64 accumulators (64 regs).
// Block: 256 thr / 8 warps, covers 8 a-rows x 32 z-pairs; warp w owns
// c-stripe [4w, 4w+4). 2 blocks/SM (reg-bound), 128KB smem/SM.

#define ZH   16384          // z-pairs (f32x2)
#define SDIM 32

using u64 = unsigned long long;

__device__ __forceinline__ u64 ffma2(u64 a, u64 b, u64 c) {
    u64 d;
    asm("fma.rn.f32x2 %0, %1, %2, %3;" : "=l"(d) : "l"(a), "l"(b), "l"(c));
    return d;
}

__global__ void __launch_bounds__(256, 2)
einnet_fused3_kernel(const u64* __restrict__ x0,
                     const u64* __restrict__ x1,
                     const u64* __restrict__ x2,
                     u64* __restrict__ out)
{
    // y1 tile: [a(8)][c(32)][lane(32)] u64 = 64KB
    extern __shared__ u64 y1s[];

    const int lane = threadIdx.x & 31;
    const int w    = threadIdx.x >> 5;            // 0..7
    const int abas = blockIdx.x * 8;              // a-group base
    const int p    = blockIdx.y * 32 + lane;      // global z-pair
    const int c0   = w * 4;                       // this warp's c/d stripe

    u64 acc[8][4];
    #pragma unroll
    for (int i = 0; i < 8; i++)
        #pragma unroll
        for (int j = 0; j < 4; j++) acc[i][j] = 0ull;

    // ---------------- Pass 1: y1[a,c] = sum_b x1[a,b] * x0[b,c] ----------------
    const u64* __restrict__ Ap = x1 + (size_t)(abas * SDIM) * ZH + p;
    const u64* __restrict__ Bp = x0 + (size_t)c0 * ZH + p;

    #pragma unroll 4
    for (int b = 0; b < SDIM; b++) {
        u64 av[8], bv[4];
        #pragma unroll
        for (int i = 0; i < 8; i++) av[i] = Ap[(size_t)(i * SDIM + b) * ZH];
        #pragma unroll
        for (int j = 0; j < 4; j++) bv[j] = Bp[(size_t)(b * SDIM + j) * ZH];
        #pragma unroll
        for (int i = 0; i < 8; i++)
            #pragma unroll
            for (int j = 0; j < 4; j++)
                acc[i][j] = ffma2(av[i], bv[j], acc[i][j]);
    }

    // store y1 stripe (conflict-free: lane-consecutive 8B)
    #pragma unroll
    for (int i = 0; i < 8; i++)
        #pragma unroll
        for (int j = 0; j < 4; j++)
            y1s[(i * SDIM + c0 + j) * 32 + lane] = acc[i][j];
    __syncthreads();

    // ---------------- Pass 2: y2[a,d] = sum_c y1[a,c] * x2[c,d] ----------------
    #pragma unroll
    for (int i = 0; i < 8; i++)
        #pragma unroll
        for (int j = 0; j < 4; j++) acc[i][j] = 0ull;

    const u64* __restrict__ Cp = x2 + (size_t)c0 * ZH + p;

    #pragma unroll 4
    for (int c = 0; c < SDIM; c++) {
        u64 yv[8], xv[4];
        #pragma unroll
        for (int j = 0; j < 4; j++) xv[j] = Cp[(size_t)(c * SDIM + j) * ZH];
        #pragma unroll
        for (int i = 0; i < 8; i++) yv[i] = y1s[(i * SDIM + c) * 32 + lane];
        #pragma unroll
        for (int i = 0; i < 8; i++)
            #pragma unroll
            for (int j = 0; j < 4; j++)
                acc[i][j] = ffma2(yv[i], xv[j], acc[i][j]);
    }

    u64* __restrict__ Op = out + (size_t)(abas * SDIM + c0) * ZH + p;
    #pragma unroll
    for (int i = 0; i < 8; i++)
        #pragma unroll
        for (int j = 0; j < 4; j++)
            Op[(size_t)(i * SDIM + j) * ZH] = acc[i][j];
}

extern "C" void kernel_launch(void* const* d_in, const int* in_sizes, int n_in,
                              void* d_out, int out_size)
{
    (void)in_sizes; (void)n_in; (void)out_size;
    const u64* x0 = (const u64*)d_in[0];   // (b, c, Z)
    const u64* x1 = (const u64*)d_in[1];   // (a, b, Z)
    const u64* x2 = (const u64*)d_in[2];   // (c, d, Z)
    u64* out = (u64*)d_out;

    constexpr int SMEM_BYTES = 8 * SDIM * 32 * 8;   // 65536
    // Idempotent, not a stream op, capture-safe.
    cudaFuncSetAttribute(einnet_fused3_kernel,
                         cudaFuncAttributeMaxDynamicSharedMemorySize, SMEM_BYTES);

    // z-tile is the slow grid dimension so the 4 a-group blocks of one z-tile
    // are co-resident and share x0/x2 slices in L1/L2.
    dim3 grid(4, ZH / 32);
    einnet_fused3_kernel<<<grid, 256, SMEM_BYTES>>>(x0, x1, x2, out);
}